// round 15
// baseline (speedup 1.0000x reference)
#include <cuda_runtime.h>
#include <math.h>

#define WPB  8          // warps per block
#define NC   1000       // classes
#define NF8  125        // 32B-chunks (8 floats) per row
#define NF4  250        // float4 per row
#define NK   10         // attack classes per row
#define L2E  1.4426950408889634f
#define NBLK 740        // 148 SMs x 5 blocks/SM, persistent

__device__ __forceinline__ float ex2f(float x) {
    float r; asm("ex2.approx.f32 %0, %1;" : "=f"(r) : "f"(x)); return r;
}
__device__ __forceinline__ float lg2f(float x) {
    float r; asm("lg2.approx.f32 %0, %1;" : "=f"(r) : "f"(x)); return r;
}
__device__ __forceinline__ float pow9f(float x) {
    float x2 = x * x, x4 = x2 * x2, x8 = x4 * x4; return x8 * x;
}
__device__ __forceinline__ float pow10f(float x) {
    float x2 = x * x, x4 = x2 * x2, x8 = x4 * x4; return x8 * x2;
}
__device__ __forceinline__ float rootf(float y, float inv_p) {
    return ex2f(lg2f(y) * inv_p);
}

struct F8 { float a[8]; };

// 256-bit load: one LDG slot carries 1KB/warp
__device__ __forceinline__ F8 ldg256(const float* p) {
    F8 v;
    unsigned r0,r1,r2,r3,r4,r5,r6,r7;
    asm("ld.global.nc.v8.b32 {%0,%1,%2,%3,%4,%5,%6,%7}, [%8];"
        : "=r"(r0),"=r"(r1),"=r"(r2),"=r"(r3),
          "=r"(r4),"=r"(r5),"=r"(r6),"=r"(r7) : "l"(p));
    v.a[0]=__int_as_float(r0); v.a[1]=__int_as_float(r1);
    v.a[2]=__int_as_float(r2); v.a[3]=__int_as_float(r3);
    v.a[4]=__int_as_float(r4); v.a[5]=__int_as_float(r5);
    v.a[6]=__int_as_float(r6); v.a[7]=__int_as_float(r7);
    return v;
}

// load one row (4 x LDG.256 per lane), -inf sentinel on the tail chunk
__device__ __forceinline__ void load_row(F8* v, const float* rowbase, int lane) {
    #pragma unroll
    for (int j = 0; j < 4; j++) {
        int i = lane + 32 * j;            // 32-byte chunk index, 0..127
        if (j < 3 || i < NF8) {
            v[j] = ldg256(rowbase + i * 8);
        } else {
            #pragma unroll
            for (int k = 0; k < 8; k++) v[j].a[k] = -INFINITY;
        }
    }
}

__global__ __launch_bounds__(WPB * 32, 5)   // target <=51 regs, 40 warps/SM
void boilerplate_loss_kernel(const float* __restrict__ y_pred,
                             const int*   __restrict__ y_attack,
                             float*       __restrict__ out,
                             int nrows)
{
    __shared__ unsigned int smask[WPB][32];   // only touched on the rare path

    const int warp   = threadIdx.x >> 5;
    const int lane   = threadIdx.x & 31;
    const int gwarp  = blockIdx.x * WPB + warp;
    const int nwarps = gridDim.x * WPB;

    F8 v[4];
    if (gwarp < nrows) load_row(v, y_pred + (size_t)gwarp * NC, lane);

    for (int row = gwarp; row < nrows; row += nwarps) {
        const float* rowbase = y_pred + (size_t)row * NC;

        // --- gather index early (independent small load) ---
        int idx = (lane < NK) ? y_attack[row * NK + lane] : 0;

        // --- consume v[] into exp-sum + unconditional max; v dies here ---
        float s0 = 0.f, s1 = 0.f;
        float mxa = -INFINITY;
        #pragma unroll
        for (int j = 0; j < 4; j++) {
            s0 += ex2f(v[j].a[0] * L2E) + ex2f(v[j].a[1] * L2E)
                + ex2f(v[j].a[2] * L2E) + ex2f(v[j].a[3] * L2E);
            s1 += ex2f(v[j].a[4] * L2E) + ex2f(v[j].a[5] * L2E)
                + ex2f(v[j].a[6] * L2E) + ex2f(v[j].a[7] * L2E);
            float m01 = fmaxf(fmaxf(v[j].a[0], v[j].a[1]), fmaxf(v[j].a[2], v[j].a[3]));
            float m23 = fmaxf(fmaxf(v[j].a[4], v[j].a[5]), fmaxf(v[j].a[6], v[j].a[7]));
            mxa = fmaxf(mxa, fmaxf(m01, m23));
        }
        float s = s0 + s1;

        // --- gather attack logits (row lines L1-hot) ---
        float xa = (lane < NK) ? __ldg(&rowbase[idx]) : 0.0f;

        // --- v[] is dead: issue NEXT row's loads into the SAME registers.
        //     They stay in flight through the whole reduction/tail below. ---
        int nxt = row + nwarps;
        if (nxt < nrows) load_row(v, y_pred + (size_t)nxt * NC, lane);

        // --- ONE fused 5-round butterfly for (s, mxa, mxatt, mnatt) ---
        float mxatt = (lane < NK) ? xa :  INFINITY;  // +inf never wins max? no — sentinel must lose:
        mxatt = (lane < NK) ? xa : -INFINITY;
        float mnatt = (lane < NK) ? xa :  INFINITY;
        #pragma unroll
        for (int o = 16; o > 0; o >>= 1) {
            s     +=        __shfl_xor_sync(0xffffffffu, s,     o);
            mxa    = fmaxf(mxa,   __shfl_xor_sync(0xffffffffu, mxa,   o));
            mxatt  = fmaxf(mxatt, __shfl_xor_sync(0xffffffffu, mxatt, o));
            mnatt  = fminf(mnatt, __shfl_xor_sync(0xffffffffu, mnatt, o));
        }

        // --- non-attack max; rare warp-uniform path reloads the (L2-hot) row ---
        float mx_non;
        if (mxa == mxatt) {
            smask[warp][lane] = 0u;
            __syncwarp();
            if (lane < NK) atomicOr(&smask[warp][idx >> 5], 1u << (idx & 31));
            __syncwarp();
            float m = -INFINITY;
            const float4* rowp4 = reinterpret_cast<const float4*>(rowbase);
            #pragma unroll 2
            for (int j = 0; j < 8; j++) {
                int i = lane + 32 * j;
                if (i < NF4) {
                    float4 q = __ldg(rowp4 + i);
                    unsigned int bits = (smask[warp][i >> 3] >> ((i & 7) * 4)) & 0xFu;
                    if (!(bits & 1u)) m = fmaxf(m, q.x);
                    if (!(bits & 2u)) m = fmaxf(m, q.y);
                    if (!(bits & 4u)) m = fmaxf(m, q.z);
                    if (!(bits & 8u)) m = fmaxf(m, q.w);
                }
            }
            #pragma unroll
            for (int o = 16; o > 0; o >>= 1)
                m = fmaxf(m, __shfl_xor_sync(0xffffffffu, m, o));
            mx_non = m;
            __syncwarp();
        } else {
            mx_non = mxa;
        }

        // --- probs + macro loss (pmin via monotonicity: exp inc, inv_s > 0) ---
        float inv_s = __frcp_rn(s);
        float pmin     = ex2f(mnatt  * L2E) * inv_s;
        float pmax_non = ex2f(mx_non * L2E) * inv_s;
        float macro = pmax_non - pmin;

        // --- sorting term: diffs of consecutive attack probs, gen-mean p=9 ---
        float p = (lane < NK) ? (ex2f(xa * L2E) * inv_s) : 0.0f;
        float pnext = __shfl_down_sync(0xffffffffu, p, 1);
        float term = 0.0f;
        if (lane < NK - 1) {
            float d  = pnext - p;              // in [-1, 1]
            float sv = 5.0f + 5.0f * d;        // surject to [0, 10]
            term = pow9f(sv);
        }
        #pragma unroll
        for (int o = 16; o > 0; o >>= 1)
            term += __shfl_xor_sync(0xffffffffu, term, o);

        if (lane == 0) {
            float gm9 = rootf(term * (1.0f / 9.0f), 1.0f / 9.0f);
            float sorting = (gm9 - 5.0f) * 0.2f;
            float c0 = 5.0f + 5.0f * macro;
            float c1 = 5.0f + 5.0f * sorting;
            float m = (pow10f(c0) + pow10f(c1)) * 0.5f;
            float fin = rootf(m, 0.1f);
            out[row] = (fin - 5.0f) * 0.2f;
        }
    }
}

extern "C" void kernel_launch(void* const* d_in, const int* in_sizes, int n_in,
                              void* d_out, int out_size)
{
    const float* y_pred   = (const float*)d_in[0];
    const int*   y_attack = (const int*)d_in[1];
    float*       out      = (float*)d_out;
    int nrows = in_sizes[1] / NK;   // 32768

    int blocks = NBLK;
    if (blocks * WPB > nrows) blocks = (nrows + WPB - 1) / WPB;
    boilerplate_loss_kernel<<<blocks, WPB * 32>>>(y_pred, y_attack, out, nrows);
}